// round 1
// baseline (speedup 1.0000x reference)
#include <cuda_runtime.h>
#include <cuda_bf16.h>
#include <math.h>

#define N_NODES 50000
#define N_EDGES 800000
#define E_TOT   (N_EDGES + N_NODES)
#define IN_DIM  128
#define HID     64
#define HEADS   4
#define OUT_DIM 20
#define NUM_GRAPHS 64
#define NEG_SLOPE 0.2f

// ---------------- scratch (static device globals; no allocation) -------------
__device__ float g_h1 [N_NODES * HEADS * HID];   // x @ W1^T           [N,256]
__device__ float g_h1o[N_NODES * HEADS * HID];   // elu(conv1 out)     [N,256]
__device__ float g_h2 [N_NODES * HID];           // h1o @ W2^T         [N,64]
__device__ float g_h2o[N_NODES * HID];           // elu(conv2 out)     [N,64]
__device__ float g_as1[N_NODES * HEADS];
__device__ float g_ad1[N_NODES * HEADS];
__device__ float g_as2[N_NODES];
__device__ float g_ad2[N_NODES];
__device__ int   g_deg   [N_NODES];
__device__ int   g_rowptr[N_NODES + 1];
__device__ int   g_woff  [N_NODES];
__device__ int   g_colsrc[E_TOT];
__device__ float g_pooled[NUM_GRAPHS * HID];

// ---------------- init ------------------------------------------------------
__global__ void k_init() {
    int i = blockIdx.x * blockDim.x + threadIdx.x;
    if (i < N_NODES) g_deg[i] = 0;
    if (i < NUM_GRAPHS * HID) ((int*)g_pooled)[i] = 0xFF800000; // -inf
}

// ---------------- SGEMM (NT): C[M,N] = A[M,K] * B[N,K]^T ---------------------
// BM=BN=64, BK=16, 256 threads, 4x4 microtile. K multiple of 16, N multiple of 64.
__global__ void k_gemm_nt(const float* __restrict__ A, const float* __restrict__ B,
                          float* __restrict__ C, int M, int N, int K) {
    __shared__ float As[16][64];
    __shared__ float Bs[16][64];
    int tid = threadIdx.x;
    int tx = tid & 15, ty = tid >> 4;
    int row0 = blockIdx.y * 64, col0 = blockIdx.x * 64;
    int lr = tid >> 2;         // 0..63
    int lc = (tid & 3) * 4;    // 0,4,8,12
    float acc[4][4] = {};
    for (int k0 = 0; k0 < K; k0 += 16) {
        int ar = row0 + lr;
        float4 av = (ar < M) ? *(const float4*)(A + (size_t)ar * K + k0 + lc)
                             : make_float4(0.f, 0.f, 0.f, 0.f);
        As[lc + 0][lr] = av.x; As[lc + 1][lr] = av.y;
        As[lc + 2][lr] = av.z; As[lc + 3][lr] = av.w;
        int br = col0 + lr;
        float4 bv = *(const float4*)(B + (size_t)br * K + k0 + lc);
        Bs[lc + 0][lr] = bv.x; Bs[lc + 1][lr] = bv.y;
        Bs[lc + 2][lr] = bv.z; Bs[lc + 3][lr] = bv.w;
        __syncthreads();
#pragma unroll
        for (int kk = 0; kk < 16; kk++) {
            float4 a = *(const float4*)&As[kk][ty * 4];
            float4 b = *(const float4*)&Bs[kk][tx * 4];
            acc[0][0] += a.x * b.x; acc[0][1] += a.x * b.y; acc[0][2] += a.x * b.z; acc[0][3] += a.x * b.w;
            acc[1][0] += a.y * b.x; acc[1][1] += a.y * b.y; acc[1][2] += a.y * b.z; acc[1][3] += a.y * b.w;
            acc[2][0] += a.z * b.x; acc[2][1] += a.z * b.y; acc[2][2] += a.z * b.z; acc[2][3] += a.z * b.w;
            acc[3][0] += a.w * b.x; acc[3][1] += a.w * b.y; acc[3][2] += a.w * b.z; acc[3][3] += a.w * b.w;
        }
        __syncthreads();
    }
#pragma unroll
    for (int i = 0; i < 4; i++) {
        int r = row0 + ty * 4 + i;
        if (r < M) {
            float4 v = make_float4(acc[i][0], acc[i][1], acc[i][2], acc[i][3]);
            *(float4*)(C + (size_t)r * N + col0 + tx * 4) = v;
        }
    }
}

// ---------------- alpha_src / alpha_dst dots (one warp per node-head) --------
template <int H>
__global__ void k_alpha(const float* __restrict__ hlin,
                        const float* __restrict__ a_s, const float* __restrict__ a_d,
                        float* __restrict__ as_o, float* __restrict__ ad_o) {
    int gw = (blockIdx.x * blockDim.x + threadIdx.x) >> 5;
    int lane = threadIdx.x & 31;
    if (gw >= N_NODES * H) return;
    int n = gw / H, h = gw % H;
    float2 hv = ((const float2*)(hlin + (size_t)n * H * HID + h * HID))[lane];
    float2 sv = ((const float2*)(a_s + h * HID))[lane];
    float2 dv = ((const float2*)(a_d + h * HID))[lane];
    float s = hv.x * sv.x + hv.y * sv.y;
    float d = hv.x * dv.x + hv.y * dv.y;
#pragma unroll
    for (int o = 16; o > 0; o >>= 1) {
        s += __shfl_xor_sync(0xffffffffu, s, o);
        d += __shfl_xor_sync(0xffffffffu, d, o);
    }
    if (lane == 0) { as_o[gw] = s; ad_o[gw] = d; }
}

// ---------------- CSR build --------------------------------------------------
__global__ void k_deg(const int* __restrict__ ei) {
    int i = blockIdx.x * blockDim.x + threadIdx.x;
    if (i >= E_TOT) return;
    int dst = (i < N_EDGES) ? ei[N_EDGES + i] : (i - N_EDGES);
    atomicAdd(&g_deg[dst], 1);
}

__global__ void k_scan() {   // single block, 1024 threads: exclusive scan of g_deg
    __shared__ int s_w[32];
    int tid = threadIdx.x, lane = tid & 31, w = tid >> 5;
    int carry = 0;
    for (int base = 0; base < N_NODES; base += 1024) {
        int i = base + tid;
        int v = (i < N_NODES) ? g_deg[i] : 0;
        int x = v;
#pragma unroll
        for (int o = 1; o < 32; o <<= 1) {
            int t = __shfl_up_sync(0xffffffffu, x, o);
            if (lane >= o) x += t;
        }
        if (lane == 31) s_w[w] = x;
        __syncthreads();
        if (w == 0) {
            int y = s_w[lane];
#pragma unroll
            for (int o = 1; o < 32; o <<= 1) {
                int t = __shfl_up_sync(0xffffffffu, y, o);
                if (lane >= o) y += t;
            }
            s_w[lane] = y;
        }
        __syncthreads();
        int woffp = (w > 0) ? s_w[w - 1] : 0;
        int excl = carry + woffp + x - v;
        if (i < N_NODES) { g_rowptr[i] = excl; g_woff[i] = excl; }
        carry += s_w[31];
        __syncthreads();
    }
    if (tid == 0) g_rowptr[N_NODES] = carry;
}

__global__ void k_scatter(const int* __restrict__ ei) {
    int i = blockIdx.x * blockDim.x + threadIdx.x;
    if (i >= E_TOT) return;
    int src, dst;
    if (i < N_EDGES) { src = ei[i]; dst = ei[N_EDGES + i]; }
    else             { src = dst = i - N_EDGES; }
    int pos = atomicAdd(&g_woff[dst], 1);
    g_colsrc[pos] = src;
}

// ---------------- GATConv gather (one warp per node-head) --------------------
// softmax over incoming edges (online max/sum) + weighted sum of h[src], + bias, + elu.
template <int H>
__global__ void k_conv(const float* __restrict__ hin,
                       const float* __restrict__ as_, const float* __restrict__ ad_,
                       const float* __restrict__ bias, float* __restrict__ hout) {
    int gw = (blockIdx.x * blockDim.x + threadIdx.x) >> 5;
    int lane = threadIdx.x & 31;
    if (gw >= N_NODES * H) return;
    int n = gw / H, h = gw % H;
    int start = g_rowptr[n], end = g_rowptr[n + 1];
    float adn = ad_[n * H + h];

    // pass 1: online softmax stats (lanes over edges)
    float m = -INFINITY, s = 0.f;
    for (int e = start + lane; e < end; e += 32) {
        int src = g_colsrc[e];
        float t = as_[src * H + h] + adn;
        t = (t >= 0.f) ? t : NEG_SLOPE * t;
        if (t > m) { s = s * __expf(m - t); m = t; }
        s += __expf(t - m);
    }
#pragma unroll
    for (int o = 16; o > 0; o >>= 1) {
        float mo = __shfl_xor_sync(0xffffffffu, m, o);
        float so = __shfl_xor_sync(0xffffffffu, s, o);
        float mn = fmaxf(m, mo);
        float s1 = (m > -INFINITY) ? s * __expf(m - mn) : 0.f;
        float s2 = (mo > -INFINITY) ? so * __expf(mo - mn) : 0.f;
        s = s1 + s2; m = mn;
    }
    float inv = 1.f / (s + 1e-16f);

    // pass 2: accumulate (lanes over channels, serial over edges)
    float acc0 = 0.f, acc1 = 0.f;
    for (int e = start; e < end; e++) {
        int src = g_colsrc[e];
        float t = as_[src * H + h] + adn;
        t = (t >= 0.f) ? t : NEG_SLOPE * t;
        float wgt = __expf(t - m) * inv;
        float2 v = ((const float2*)(hin + (size_t)src * (H * HID) + h * HID))[lane];
        acc0 += v.x * wgt;
        acc1 += v.y * wgt;
    }
    float o0 = acc0 + bias[h * HID + 2 * lane];
    float o1 = acc1 + bias[h * HID + 2 * lane + 1];
    o0 = (o0 > 0.f) ? o0 : expm1f(o0);   // elu
    o1 = (o1 > 0.f) ? o1 : expm1f(o1);
    ((float2*)(hout + (size_t)n * (H * HID) + h * HID))[lane] = make_float2(o0, o1);
}

// ---------------- pooling: segment_max over batch ----------------------------
__global__ void k_pool(const int* __restrict__ batch) {
    int idx = blockIdx.x * blockDim.x + threadIdx.x;
    if (idx >= N_NODES * HID) return;
    int n = idx >> 6, c = idx & 63;
    float v = g_h2o[idx];
    int g = batch[n];
    float* addr = &g_pooled[g * HID + c];
    if (v >= 0.f) atomicMax((int*)addr, __float_as_int(v));
    else          atomicMin((unsigned int*)addr, __float_as_uint(v));
}

// ---------------- final FC ---------------------------------------------------
__global__ void k_fc(const float* __restrict__ fcW, const float* __restrict__ fcb,
                     float* __restrict__ out) {
    int i = blockIdx.x * blockDim.x + threadIdx.x;
    if (i >= NUM_GRAPHS * OUT_DIM) return;
    int g = i / OUT_DIM, o = i % OUT_DIM;
    float acc = fcb[o];
#pragma unroll
    for (int c = 0; c < HID; c++)
        acc += g_pooled[g * HID + c] * fcW[o * HID + c];
    out[i] = acc;
}

// ---------------- launch -----------------------------------------------------
extern "C" void kernel_launch(void* const* d_in, const int* in_sizes, int n_in,
                              void* d_out, int out_size) {
    const float* x      = (const float*)d_in[0];
    const int*   ei     = (const int*)  d_in[1];
    const int*   batch  = (const int*)  d_in[2];
    const float* W1     = (const float*)d_in[3];
    const float* a_src1 = (const float*)d_in[4];
    const float* a_dst1 = (const float*)d_in[5];
    const float* b1     = (const float*)d_in[6];
    const float* W2     = (const float*)d_in[7];
    const float* a_src2 = (const float*)d_in[8];
    const float* a_dst2 = (const float*)d_in[9];
    const float* b2     = (const float*)d_in[10];
    const float* fcW    = (const float*)d_in[11];
    const float* fcb    = (const float*)d_in[12];
    float* out = (float*)d_out;

    float *h1, *h1o, *h2, *h2o, *as1, *ad1, *as2, *ad2;
    cudaGetSymbolAddress((void**)&h1,  g_h1);
    cudaGetSymbolAddress((void**)&h1o, g_h1o);
    cudaGetSymbolAddress((void**)&h2,  g_h2);
    cudaGetSymbolAddress((void**)&h2o, g_h2o);
    cudaGetSymbolAddress((void**)&as1, g_as1);
    cudaGetSymbolAddress((void**)&ad1, g_ad1);
    cudaGetSymbolAddress((void**)&as2, g_as2);
    cudaGetSymbolAddress((void**)&ad2, g_ad2);

    const int B = 256;

    // init (deg zero + pooled -inf)
    k_init<<<(N_NODES + B - 1) / B, B>>>();

    // CSR build (reused by both layers)
    k_deg<<<(E_TOT + B - 1) / B, B>>>(ei);
    k_scan<<<1, 1024>>>();
    k_scatter<<<(E_TOT + B - 1) / B, B>>>(ei);

    // layer 1: linear -> alpha -> gather-softmax-aggregate (+bias, elu)
    {
        dim3 grid((HEADS * HID) / 64, (N_NODES + 63) / 64);
        k_gemm_nt<<<grid, B>>>(x, W1, h1, N_NODES, HEADS * HID, IN_DIM);
    }
    k_alpha<HEADS><<<(N_NODES * HEADS * 32 + B - 1) / B, B>>>(h1, a_src1, a_dst1, as1, ad1);
    k_conv<HEADS><<<(N_NODES * HEADS * 32 + B - 1) / B, B>>>(h1, as1, ad1, b1, h1o);

    // layer 2
    {
        dim3 grid(HID / 64, (N_NODES + 63) / 64);
        k_gemm_nt<<<grid, B>>>(h1o, W2, h2, N_NODES, HID, HEADS * HID);
    }
    k_alpha<1><<<(N_NODES * 32 + B - 1) / B, B>>>(h2, a_src2, a_dst2, as2, ad2);
    k_conv<1><<<(N_NODES * 32 + B - 1) / B, B>>>(h2, as2, ad2, b2, h2o);

    // pool + fc
    k_pool<<<(N_NODES * HID + B - 1) / B, B>>>(batch);
    k_fc<<<(NUM_GRAPHS * OUT_DIM + B - 1) / B, B>>>(fcW, fcb, out);
}